// round 1
// baseline (speedup 1.0000x reference)
#include <cuda_runtime.h>
#include <cuda_bf16.h>
#include <math.h>
#include <float.h>

// ============================================================================
// DeepSeekV3 MoE Gate:
//   logits = x @ W^T  (T=8192, H=7168, E=256)
//   s = sigmoid(logits); sb = s + bias
//   group score = sum(top2(sb within 32-expert group)); top-4 of 8 groups
//   top-8 experts among selected groups by sb (jax top_k tie: lower idx first)
//   weights = s[idx] / sum(s[idx]) * 2.5
// Output layout (float32): [ T*8 indices (as float) | T*8 weights ]
// ============================================================================

#define N_EXPERTS 256
#define N_GROUP   8
#define GROUP_SZ  32   // experts per group
#define TOPK_GRP  4
#define TOP_K     8
#define SCALE     2.5f

#define MAX_T 8192
__device__ float g_logits[MAX_T * N_EXPERTS];   // scratch: raw router logits

// ---------------------------------------------------------------------------
// Kernel 1: tiled fp32 GEMM  logits[T][256] = x[T][H] * W[256][H]^T
// BM=64 tokens, BN=256 experts (full), BK=32. 256 threads.
// Thread (tx=tid&31, ty=tid>>5) computes 8 tokens x 8 experts:
//   tokens  = blk*64 + ty*8 + i          (i = 0..7)
//   experts = {4*tx+j, 128+4*tx+j}       (j = 0..3 each)  -> conflict-free LDS.128
// ---------------------------------------------------------------------------
#define BM 64
#define BN 256
#define BK 32

__global__ __launch_bounds__(256)
void moe_gemm_kernel(const float* __restrict__ x, const float* __restrict__ w,
                     int T, int H)
{
    __shared__ float xs[BK][BM + 4];   // [32][68]  row stride 272B (16B aligned)
    __shared__ float ws[BK][BN + 4];   // [32][260] row stride 1040B (16B aligned)

    const int tid = threadIdx.x;
    const int tx  = tid & 31;
    const int ty  = tid >> 5;
    const int row0 = blockIdx.x * BM;

    float acc[8][8];
#pragma unroll
    for (int i = 0; i < 8; i++)
#pragma unroll
        for (int j = 0; j < 8; j++) acc[i][j] = 0.0f;

    // register staging buffers
    float4 rx[2];
    float4 rw[8];

    // prologue: load first tile into registers
    {
        const int k0 = 0;
#pragma unroll
        for (int l = 0; l < 2; l++) {
            int q = tid + 256 * l;           // 0..511
            int token = q >> 3, kq = q & 7;
            rx[l] = *reinterpret_cast<const float4*>(&x[(size_t)(row0 + token) * H + k0 + kq * 4]);
        }
#pragma unroll
        for (int l = 0; l < 8; l++) {
            int q = tid + 256 * l;           // 0..2047
            int e = q >> 3, kq = q & 7;
            rw[l] = *reinterpret_cast<const float4*>(&w[(size_t)e * H + k0 + kq * 4]);
        }
    }

    for (int t = 0; t < H; t += BK) {
        __syncthreads();   // previous compute done; safe to overwrite smem

        // store staged registers to smem (transposed to [k][m] / [k][e])
#pragma unroll
        for (int l = 0; l < 2; l++) {
            int q = tid + 256 * l;
            int token = q >> 3, kq = q & 7;
            xs[kq * 4 + 0][token] = rx[l].x;
            xs[kq * 4 + 1][token] = rx[l].y;
            xs[kq * 4 + 2][token] = rx[l].z;
            xs[kq * 4 + 3][token] = rx[l].w;
        }
#pragma unroll
        for (int l = 0; l < 8; l++) {
            int q = tid + 256 * l;
            int e = q >> 3, kq = q & 7;
            ws[kq * 4 + 0][e] = rw[l].x;
            ws[kq * 4 + 1][e] = rw[l].y;
            ws[kq * 4 + 2][e] = rw[l].z;
            ws[kq * 4 + 3][e] = rw[l].w;
        }
        __syncthreads();   // smem tile ready

        // prefetch next tile into registers
        if (t + BK < H) {
            const int k0 = t + BK;
#pragma unroll
            for (int l = 0; l < 2; l++) {
                int q = tid + 256 * l;
                int token = q >> 3, kq = q & 7;
                rx[l] = *reinterpret_cast<const float4*>(&x[(size_t)(row0 + token) * H + k0 + kq * 4]);
            }
#pragma unroll
            for (int l = 0; l < 8; l++) {
                int q = tid + 256 * l;
                int e = q >> 3, kq = q & 7;
                rw[l] = *reinterpret_cast<const float4*>(&w[(size_t)e * H + k0 + kq * 4]);
            }
        }

        // compute on the tile in smem
#pragma unroll
        for (int k = 0; k < BK; k++) {
            float a[8], b[8];
            float4 av0 = *reinterpret_cast<const float4*>(&xs[k][ty * 8]);
            float4 av1 = *reinterpret_cast<const float4*>(&xs[k][ty * 8 + 4]);
            a[0]=av0.x; a[1]=av0.y; a[2]=av0.z; a[3]=av0.w;
            a[4]=av1.x; a[5]=av1.y; a[6]=av1.z; a[7]=av1.w;
            float4 bv0 = *reinterpret_cast<const float4*>(&ws[k][tx * 4]);
            float4 bv1 = *reinterpret_cast<const float4*>(&ws[k][128 + tx * 4]);
            b[0]=bv0.x; b[1]=bv0.y; b[2]=bv0.z; b[3]=bv0.w;
            b[4]=bv1.x; b[5]=bv1.y; b[6]=bv1.z; b[7]=bv1.w;
#pragma unroll
            for (int i = 0; i < 8; i++)
#pragma unroll
                for (int j = 0; j < 8; j++)
                    acc[i][j] = fmaf(a[i], b[j], acc[i][j]);
        }
    }

    // write logits: token t -> experts [4tx..4tx+3] and [128+4tx..128+4tx+3]
#pragma unroll
    for (int i = 0; i < 8; i++) {
        int token = row0 + ty * 8 + i;
        float4 v0 = make_float4(acc[i][0], acc[i][1], acc[i][2], acc[i][3]);
        float4 v1 = make_float4(acc[i][4], acc[i][5], acc[i][6], acc[i][7]);
        *reinterpret_cast<float4*>(&g_logits[(size_t)token * N_EXPERTS + tx * 4])       = v0;
        *reinterpret_cast<float4*>(&g_logits[(size_t)token * N_EXPERTS + 128 + tx * 4]) = v1;
    }
}

// ---------------------------------------------------------------------------
// Kernel 2: per-token grouped top-k. One warp per token.
// Lane holds expert e = j*32 + lane for j = 0..7  (so register slot j == group j)
// ---------------------------------------------------------------------------
__global__ __launch_bounds__(256)
void moe_topk_kernel(const float* __restrict__ bias, float* __restrict__ out, int T)
{
    const unsigned FULL = 0xFFFFFFFFu;
    const int lane   = threadIdx.x & 31;
    const int warpId = threadIdx.x >> 5;
    const int t = blockIdx.x * 8 + warpId;
    if (t >= T) return;

    const float* lg = &g_logits[(size_t)t * N_EXPERTS];

    float s[8], sb[8];
#pragma unroll
    for (int j = 0; j < 8; j++) {
        int e = j * 32 + lane;
        float logit = lg[e];
        float sv = 1.0f / (1.0f + expf(-logit));
        s[j]  = sv;
        sb[j] = sv + bias[e];
    }

    // per-group top-2 sum (group j lives entirely in register slot j across lanes)
    float gs[8];
#pragma unroll
    for (int g = 0; g < 8; g++) {
        float m1 = sb[g], m2 = -FLT_MAX;
#pragma unroll
        for (int off = 16; off >= 1; off >>= 1) {
            float o1 = __shfl_xor_sync(FULL, m1, off);
            float o2 = __shfl_xor_sync(FULL, m2, off);
            float hi = fmaxf(m1, o1);
            float lo = fminf(m1, o1);
            m2 = fmaxf(lo, fmaxf(m2, o2));
            m1 = hi;
        }
        gs[g] = m1 + m2;   // identical on all lanes
    }

    // top-4 groups (tie -> lower group index, matching jax top_k)
    unsigned gmask = 0;
#pragma unroll
    for (int r = 0; r < TOPK_GRP; r++) {
        float best = -FLT_MAX; int bg = 0;
#pragma unroll
        for (int g = 0; g < 8; g++) {
            bool taken = (gmask >> g) & 1u;
            if (!taken && gs[g] > best) { best = gs[g]; bg = g; }
        }
        gmask |= (1u << bg);
    }

    // masked candidates
    float v[8];
#pragma unroll
    for (int j = 0; j < 8; j++)
        v[j] = ((gmask >> j) & 1u) ? sb[j] : -FLT_MAX;

    // 8 rounds of warp argmax (value desc, tie -> smaller expert index)
    float wts[TOP_K];
    int   idxs[TOP_K];
    float wsum = 0.0f;
#pragma unroll
    for (int r = 0; r < TOP_K; r++) {
        float bv = -FLT_MAX; int bj = -1;
#pragma unroll
        for (int j = 0; j < 8; j++)
            if (v[j] > bv) { bv = v[j]; bj = j; }
        int bidx = (bj >= 0) ? (bj * 32 + lane) : (N_EXPERTS + lane);  // sentinel

        float cv = bv; int ci = bidx;
#pragma unroll
        for (int off = 16; off >= 1; off >>= 1) {
            float ov = __shfl_xor_sync(FULL, cv, off);
            int   oi = __shfl_xor_sync(FULL, ci, off);
            if (ov > cv || (ov == cv && oi < ci)) { cv = ov; ci = oi; }
        }
        // ci identical on all lanes; winner = lane (ci&31), slot (ci>>5)
        int wl = ci & 31;
        int wj = ci >> 5;
        float sv_local = 0.0f;
#pragma unroll
        for (int j = 0; j < 8; j++) if (j == wj) sv_local = s[j];
        float sv = __shfl_sync(FULL, sv_local, wl);

        idxs[r] = ci;
        wts[r]  = sv;
        wsum   += sv;

        if (lane == wl) {
#pragma unroll
            for (int j = 0; j < 8; j++) if (j == wj) v[j] = -FLT_MAX;
        }
    }

    if (lane == 0) {
        float inv = SCALE / wsum;
        size_t half = (size_t)T * TOP_K;
#pragma unroll
        for (int r = 0; r < TOP_K; r++) {
            out[(size_t)t * TOP_K + r]        = (float)idxs[r];
            out[half + (size_t)t * TOP_K + r] = wts[r] * inv;
        }
    }
}

// ---------------------------------------------------------------------------
extern "C" void kernel_launch(void* const* d_in, const int* in_sizes, int n_in,
                              void* d_out, int out_size)
{
    const float* x    = (const float*)d_in[0];   // [B,S,H] fp32
    const float* w    = (const float*)d_in[1];   // [E,H]   fp32
    const float* bias = (const float*)d_in[2];   // [E]     fp32
    float* out = (float*)d_out;

    const int E = in_sizes[2];                   // 256
    const int H = in_sizes[1] / E;               // 7168
    const int T = in_sizes[0] / H;               // 8192

    dim3 gemmGrid(T / BM);
    moe_gemm_kernel<<<gemmGrid, 256>>>(x, w, T, H);

    dim3 topkGrid((T + 7) / 8);
    moe_topk_kernel<<<topkGrid, 256>>>(bias, out, T);
}

// round 4
// speedup vs baseline: 1.6724x; 1.6724x over previous
#include <cuda_runtime.h>
#include <cuda_bf16.h>
#include <math.h>
#include <float.h>
#include <stdint.h>

// ============================================================================
// DeepSeekV3 MoE Gate (sm_103a; PTX target compute_103 -> no tcgen05).
// GEMM via mma.sync.m16n8k16 bf16 with bf16x3 fp32-emulation split and
// periodic RN accumulator flush (defeats tensor-core RZ-accumulate drift).
//   logits = x @ W^T  (T=8192, H=7168, E=256)
//   then sigmoid/bias/grouped top-k
// Output (float32): [ T*8 indices (as float) | T*8 weights ]
// ============================================================================

#define N_EXPERTS 256
#define TOPK_GRP  4
#define TOP_K     8
#define SCALE     2.5f
#define H_DIM     7168
#define MAX_T     8192

__device__ float g_logits[MAX_T * N_EXPERTS];                       // 8 MB
__device__ __align__(16) __nv_bfloat16 g_w1[N_EXPERTS * H_DIM];     // W hi
__device__ __align__(16) __nv_bfloat16 g_w2[N_EXPERTS * H_DIM];     // W mid
__device__ __align__(16) __nv_bfloat16 g_w3[N_EXPERTS * H_DIM];     // W lo

// ---------------------------------------------------------------------------
// helpers
// ---------------------------------------------------------------------------
__device__ __forceinline__ uint32_t smem_to_u32(const void* p) {
    uint32_t a;
    asm("{ .reg .u64 t; cvta.to.shared.u64 t, %1; cvt.u32.u64 %0, t; }"
        : "=r"(a) : "l"(p));
    return a;
}
__device__ __forceinline__ void cp16(uint32_t dst, const void* src) {
    asm volatile("cp.async.cg.shared.global [%0], [%1], 16;" :: "r"(dst), "l"(src));
}
#define CP_COMMIT() asm volatile("cp.async.commit_group;" ::: "memory")
#define CP_WAIT1()  asm volatile("cp.async.wait_group 1;" ::: "memory")

__device__ __forceinline__ void ldmatrix_x4(uint32_t* r, uint32_t addr) {
    asm volatile("ldmatrix.sync.aligned.m8n8.x4.shared.b16 {%0,%1,%2,%3}, [%4];"
                 : "=r"(r[0]), "=r"(r[1]), "=r"(r[2]), "=r"(r[3]) : "r"(addr));
}
__device__ __forceinline__ void mma_bf16(float* d, const uint32_t* a,
                                         uint32_t b0, uint32_t b1) {
    asm volatile(
        "mma.sync.aligned.m16n8k16.row.col.f32.bf16.bf16.f32 "
        "{%0,%1,%2,%3}, {%4,%5,%6,%7}, {%8,%9}, {%0,%1,%2,%3};"
        : "+f"(d[0]), "+f"(d[1]), "+f"(d[2]), "+f"(d[3])
        : "r"(a[0]), "r"(a[1]), "r"(a[2]), "r"(a[3]), "r"(b0), "r"(b1));
}

// split a float2 into 3 packed bf16x2 (hi, mid, lo); low 16 bits = f.x
__device__ __forceinline__ void split3(float2 f, uint32_t& h, uint32_t& m, uint32_t& l) {
    __nv_bfloat162 bh = __floats2bfloat162_rn(f.x, f.y);
    h = *reinterpret_cast<uint32_t*>(&bh);
    float hx = __uint_as_float((h & 0xFFFFu) << 16);
    float hy = __uint_as_float(h & 0xFFFF0000u);
    float rx = f.x - hx, ry = f.y - hy;
    __nv_bfloat162 bm = __floats2bfloat162_rn(rx, ry);
    m = *reinterpret_cast<uint32_t*>(&bm);
    float mx = __uint_as_float((m & 0xFFFFu) << 16);
    float my = __uint_as_float(m & 0xFFFF0000u);
    __nv_bfloat162 bl = __floats2bfloat162_rn(rx - mx, ry - my);
    l = *reinterpret_cast<uint32_t*>(&bl);
}

// ---------------------------------------------------------------------------
// Kernel 0: split fp32 weights -> 3 bf16 tensors
// ---------------------------------------------------------------------------
__global__ __launch_bounds__(256)
void split_w_kernel(const float* __restrict__ w)
{
    int i = blockIdx.x * 256 + threadIdx.x;           // one float4 per thread
    const int n4 = N_EXPERTS * H_DIM / 4;
    if (i >= n4) return;
    float4 v = reinterpret_cast<const float4*>(w)[i];
    uint32_t h0, m0, l0, h1, m1, l1;
    split3(make_float2(v.x, v.y), h0, m0, l0);
    split3(make_float2(v.z, v.w), h1, m1, l1);
    reinterpret_cast<uint2*>(g_w1)[i] = make_uint2(h0, h1);
    reinterpret_cast<uint2*>(g_w2)[i] = make_uint2(m0, m1);
    reinterpret_cast<uint2*>(g_w3)[i] = make_uint2(l0, l1);
}

// ---------------------------------------------------------------------------
// Kernel 1: GEMM via mma.sync bf16x3 + RN flush.
// CTA: 128 tokens x 128 experts. BK=32. 3-stage cp.async pipeline.
// smem: A fp32 [128][40] (160B rows), B bf16x3 [3][128][40] (80B rows)
// warps: 4(m) x 2(n); warp tile 32 x 64; accum 2x8 m16n8 microtiles.
// ---------------------------------------------------------------------------
#define BK        32
#define NCHUNK    (H_DIM / BK)          // 224
#define FLUSH_MASK 7                    // flush every 8 chunks (K=256)
#define A_BYTES   (128 * 160)           // 20480
#define B_SPLIT_B (128 * 80)            // 10240
#define STAGE_B   (A_BYTES + 3 * B_SPLIT_B)  // 51200
#define GEMM_SMEM (3 * STAGE_B)              // 153600

__device__ __forceinline__ void load_stage(const float* __restrict__ x,
                                           int row0, int e0, int k0,
                                           uint32_t stage_base, int tid)
{
    // A: 128 rows x 32 fp32 (128B payload per row, row stride 160B)
#pragma unroll
    for (int l = 0; l < 4; l++) {
        int q = tid + 256 * l;             // 0..1023
        int row = q >> 3, seg = q & 7;
        const float* src = x + (size_t)(row0 + row) * H_DIM + k0 + seg * 4;
        cp16(stage_base + row * 160 + seg * 16, src);
    }
    // B: 3 splits x 128 rows x 32 bf16 (64B payload per row, stride 80B)
#pragma unroll
    for (int l = 0; l < 6; l++) {
        int q = tid + 256 * l;             // 0..1535
        int s = q >> 9;                    // split
        int r = q & 511;
        int row = r >> 2, seg = r & 3;
        const __nv_bfloat16* wp = (s == 0) ? g_w1 : (s == 1) ? g_w2 : g_w3;
        const __nv_bfloat16* src = wp + (size_t)(e0 + row) * H_DIM + k0 + seg * 8;
        cp16(stage_base + A_BYTES + s * B_SPLIT_B + row * 80 + seg * 16, src);
    }
}

__global__ __launch_bounds__(256, 1)
void moe_gemm_mma(const float* __restrict__ x)
{
    extern __shared__ char smem[];
    const uint32_t sbase = smem_to_u32(smem);
    const int tid  = threadIdx.x;
    const int lane = tid & 31;
    const int wid  = tid >> 5;
    const int wm   = wid & 3;              // warp row (m)
    const int wn   = wid >> 2;             // warp col (n)
    const int row0 = blockIdx.x * 128;
    const int e0   = blockIdx.y * 128;

    float acc[2][8][4];                    // short-chain accumulators
    float master[2][8][4];                 // RN-summed masters
#pragma unroll
    for (int mt = 0; mt < 2; mt++)
#pragma unroll
        for (int nt = 0; nt < 8; nt++)
#pragma unroll
            for (int q = 0; q < 4; q++) { acc[mt][nt][q] = 0.0f; master[mt][nt][q] = 0.0f; }

    // prologue: stages 0,1
    load_stage(x, row0, e0, 0,  sbase + 0 * STAGE_B, tid); CP_COMMIT();
    load_stage(x, row0, e0, BK, sbase + 1 * STAGE_B, tid); CP_COMMIT();

    const int c2 = (lane & 3) * 2;         // k-pair base within 8

    for (int c = 0; c < NCHUNK; ++c) {
        CP_WAIT1();
        __syncthreads();

        if (c + 2 < NCHUNK)
            load_stage(x, row0, e0, (c + 2) * BK, sbase + ((c + 2) % 3) * STAGE_B, tid);
        CP_COMMIT();

        const int slot = c % 3;
        const char* As = smem + slot * STAGE_B;
        const uint32_t Bs = sbase + slot * STAGE_B + A_BYTES;

#pragma unroll
        for (int kk = 0; kk < 2; kk++) {           // two k16 steps per BK=32
            // ---- A fragments: load fp32 pairs, split to bf16x3 ----
            uint32_t a[3][2][4];
#pragma unroll
            for (int mt = 0; mt < 2; mt++) {
                int brow = wm * 32 + mt * 16 + (lane >> 2);
#pragma unroll
                for (int q = 0; q < 4; q++) {
                    int r   = brow + (q & 1) * 8;
                    int col = kk * 16 + c2 + (q >> 1) * 8;
                    float2 f = *reinterpret_cast<const float2*>(As + (r * 40 + col) * 4);
                    split3(f, a[0][mt][q], a[1][mt][q], a[2][mt][q]);
                }
            }
            // ---- passes grouped by B split: only one b-set live ----
            // s=0 (W_hi): a_hi, a_mid, a_lo ; s=1 (W_mid): a_hi, a_mid ; s=2 (W_lo): a_hi
#pragma unroll
            for (int s = 0; s < 3; s++) {
                uint32_t b[4][4];
#pragma unroll
                for (int p = 0; p < 4; p++) {
                    int row = wn * 64 + p * 16 + (lane & 7) + ((lane >> 4) & 1) * 8;
                    uint32_t addr = Bs + s * B_SPLIT_B + row * 80
                                  + kk * 32 + ((lane >> 3) & 1) * 16;
                    ldmatrix_x4(b[p], addr);
                }
                const int npass = (s == 0) ? 3 : (s == 1) ? 2 : 1;
#pragma unroll
                for (int ai = 0; ai < 3; ai++) {
                    if (ai < npass) {
#pragma unroll
                        for (int mt = 0; mt < 2; mt++)
#pragma unroll
                            for (int nt = 0; nt < 8; nt++) {
                                int p = nt >> 1, o = (nt & 1) * 2;
                                mma_bf16(acc[mt][nt], a[ai][mt], b[p][o], b[p][o + 1]);
                            }
                    }
                }
            }
        }

        // ---- RN flush: keep tensor-core accumulation chains short ----
        if ((c & FLUSH_MASK) == FLUSH_MASK) {
#pragma unroll
            for (int mt = 0; mt < 2; mt++)
#pragma unroll
                for (int nt = 0; nt < 8; nt++)
#pragma unroll
                    for (int q = 0; q < 4; q++) {
                        master[mt][nt][q] += acc[mt][nt][q];
                        acc[mt][nt][q] = 0.0f;
                    }
        }
    }

    // fold any residual (NCHUNK % 8 == 0 -> acc already zero, harmless)
#pragma unroll
    for (int mt = 0; mt < 2; mt++)
#pragma unroll
        for (int nt = 0; nt < 8; nt++)
#pragma unroll
            for (int q = 0; q < 4; q++) master[mt][nt][q] += acc[mt][nt][q];

    // epilogue: write logits
#pragma unroll
    for (int mt = 0; mt < 2; mt++) {
        int row = row0 + wm * 32 + mt * 16 + (lane >> 2);
#pragma unroll
        for (int nt = 0; nt < 8; nt++) {
            int col = e0 + wn * 64 + nt * 8 + c2;
            *reinterpret_cast<float2*>(&g_logits[(size_t)row * N_EXPERTS + col]) =
                make_float2(master[mt][nt][0], master[mt][nt][1]);
            *reinterpret_cast<float2*>(&g_logits[(size_t)(row + 8) * N_EXPERTS + col]) =
                make_float2(master[mt][nt][2], master[mt][nt][3]);
        }
    }
}

// ---------------------------------------------------------------------------
// Kernel 2: per-token grouped top-k. One warp per token.
// ---------------------------------------------------------------------------
__global__ __launch_bounds__(256)
void moe_topk_kernel(const float* __restrict__ bias, float* __restrict__ out, int T)
{
    const unsigned FULL = 0xFFFFFFFFu;
    const int lane   = threadIdx.x & 31;
    const int warpId = threadIdx.x >> 5;
    const int t = blockIdx.x * 8 + warpId;
    if (t >= T) return;

    const float* lg = &g_logits[(size_t)t * N_EXPERTS];

    float s[8], sb[8];
#pragma unroll
    for (int j = 0; j < 8; j++) {
        int e = j * 32 + lane;
        float logit = lg[e];
        float sv = 1.0f / (1.0f + expf(-logit));
        s[j]  = sv;
        sb[j] = sv + bias[e];
    }

    float gs[8];
#pragma unroll
    for (int g = 0; g < 8; g++) {
        float m1 = sb[g], m2 = -FLT_MAX;
#pragma unroll
        for (int off = 16; off >= 1; off >>= 1) {
            float o1 = __shfl_xor_sync(FULL, m1, off);
            float o2 = __shfl_xor_sync(FULL, m2, off);
            float hi = fmaxf(m1, o1);
            float lo = fminf(m1, o1);
            m2 = fmaxf(lo, fmaxf(m2, o2));
            m1 = hi;
        }
        gs[g] = m1 + m2;
    }

    unsigned gmask = 0;
#pragma unroll
    for (int r = 0; r < TOPK_GRP; r++) {
        float best = -FLT_MAX; int bg = 0;
#pragma unroll
        for (int g = 0; g < 8; g++) {
            bool taken = (gmask >> g) & 1u;
            if (!taken && gs[g] > best) { best = gs[g]; bg = g; }
        }
        gmask |= (1u << bg);
    }

    float v[8];
#pragma unroll
    for (int j = 0; j < 8; j++)
        v[j] = ((gmask >> j) & 1u) ? sb[j] : -FLT_MAX;

    float wts[TOP_K];
    int   idxs[TOP_K];
    float wsum = 0.0f;
#pragma unroll
    for (int r = 0; r < TOP_K; r++) {
        float bv = -FLT_MAX; int bj = -1;
#pragma unroll
        for (int j = 0; j < 8; j++)
            if (v[j] > bv) { bv = v[j]; bj = j; }
        int bidx = (bj >= 0) ? (bj * 32 + lane) : (N_EXPERTS + lane);

        float cv = bv; int ci = bidx;
#pragma unroll
        for (int off = 16; off >= 1; off >>= 1) {
            float ov = __shfl_xor_sync(FULL, cv, off);
            int   oi = __shfl_xor_sync(FULL, ci, off);
            if (ov > cv || (ov == cv && oi < ci)) { cv = ov; ci = oi; }
        }
        int wl = ci & 31;
        int wj = ci >> 5;
        float sv_local = 0.0f;
#pragma unroll
        for (int j = 0; j < 8; j++) if (j == wj) sv_local = s[j];
        float sv = __shfl_sync(FULL, sv_local, wl);

        idxs[r] = ci;
        wts[r]  = sv;
        wsum   += sv;

        if (lane == wl) {
#pragma unroll
            for (int j = 0; j < 8; j++) if (j == wj) v[j] = -FLT_MAX;
        }
    }

    if (lane == 0) {
        float inv = SCALE / wsum;
        size_t half = (size_t)T * TOP_K;
#pragma unroll
        for (int r = 0; r < TOP_K; r++) {
            out[(size_t)t * TOP_K + r]        = (float)idxs[r];
            out[half + (size_t)t * TOP_K + r] = wts[r] * inv;
        }
    }
}

// ---------------------------------------------------------------------------
extern "C" void kernel_launch(void* const* d_in, const int* in_sizes, int n_in,
                              void* d_out, int out_size)
{
    const float* x    = (const float*)d_in[0];   // [B,S,H] fp32
    const float* w    = (const float*)d_in[1];   // [E,H]   fp32
    const float* bias = (const float*)d_in[2];   // [E]     fp32
    float* out = (float*)d_out;

    const int E = in_sizes[2];                   // 256
    const int H = in_sizes[1] / E;               // 7168
    const int T = in_sizes[0] / H;               // 8192

    // 0) split weights into bf16x3
    {
        int n4 = E * H / 4;
        split_w_kernel<<<(n4 + 255) / 256, 256>>>(w);
    }

    // 1) tensor-core GEMM -> g_logits
    cudaFuncSetAttribute(moe_gemm_mma,
                         cudaFuncAttributeMaxDynamicSharedMemorySize, GEMM_SMEM);
    dim3 gemmGrid(T / 128, E / 128);             // (64, 2)
    moe_gemm_mma<<<gemmGrid, 256, GEMM_SMEM>>>(x);

    // 2) grouped top-k
    dim3 topkGrid((T + 7) / 8);
    moe_topk_kernel<<<topkGrid, 256>>>(bias, out, T);
}

// round 5
// speedup vs baseline: 2.1729x; 1.2993x over previous
#include <cuda_runtime.h>
#include <cuda_fp16.h>
#include <math.h>
#include <float.h>
#include <stdint.h>

// ============================================================================
// DeepSeekV3 MoE Gate (sm_103a; PTX target compute_103 -> no tcgen05).
// GEMM via mma.sync.m16n8k16 fp16 with fp16x2 split (W prescaled x64 so all
// 4 product passes share one fp32 accumulator) + periodic RN master flush.
//   logits = x @ W^T  (T=8192, H=7168, E=256)
//   then sigmoid/bias/grouped top-k
// Output (float32): [ T*8 indices (as float) | T*8 weights ]
// ============================================================================

#define N_EXPERTS 256
#define TOPK_GRP  4
#define TOP_K     8
#define SCALE     2.5f
#define H_DIM     7168
#define MAX_T     8192
#define W_PRESCALE   64.0f
#define W_POSTSCALE  0.015625f   // 1/64

__device__ float g_logits[MAX_T * N_EXPERTS];                 // 8 MB
__device__ __align__(16) __half g_wh[N_EXPERTS * H_DIM];      // fp16(64*w)
__device__ __align__(16) __half g_wm[N_EXPERTS * H_DIM];      // fp16(64*w - hi)

// ---------------------------------------------------------------------------
// helpers
// ---------------------------------------------------------------------------
__device__ __forceinline__ uint32_t smem_to_u32(const void* p) {
    uint32_t a;
    asm("{ .reg .u64 t; cvta.to.shared.u64 t, %1; cvt.u32.u64 %0, t; }"
        : "=r"(a) : "l"(p));
    return a;
}
__device__ __forceinline__ void cp16(uint32_t dst, const void* src) {
    asm volatile("cp.async.cg.shared.global [%0], [%1], 16;" :: "r"(dst), "l"(src));
}
#define CP_COMMIT() asm volatile("cp.async.commit_group;" ::: "memory")
#define CP_WAIT1()  asm volatile("cp.async.wait_group 1;" ::: "memory")

__device__ __forceinline__ void ldmatrix_x4(uint32_t* r, uint32_t addr) {
    asm volatile("ldmatrix.sync.aligned.m8n8.x4.shared.b16 {%0,%1,%2,%3}, [%4];"
                 : "=r"(r[0]), "=r"(r[1]), "=r"(r[2]), "=r"(r[3]) : "r"(addr));
}
__device__ __forceinline__ void mma_fp16(float* d, const uint32_t* a,
                                         uint32_t b0, uint32_t b1) {
    asm volatile(
        "mma.sync.aligned.m16n8k16.row.col.f32.f16.f16.f32 "
        "{%0,%1,%2,%3}, {%4,%5,%6,%7}, {%8,%9}, {%0,%1,%2,%3};"
        : "+f"(d[0]), "+f"(d[1]), "+f"(d[2]), "+f"(d[3])
        : "r"(a[0]), "r"(a[1]), "r"(a[2]), "r"(a[3]), "r"(b0), "r"(b1));
}

// split a float2 into 2 packed fp16x2 (hi, mid); low 16 bits = f.x
__device__ __forceinline__ void split2(float2 f, uint32_t& h, uint32_t& m) {
    __half2 hh = __floats2half2_rn(f.x, f.y);
    h = *reinterpret_cast<uint32_t*>(&hh);
    float2 hf = __half22float2(hh);
    __half2 mm2 = __floats2half2_rn(f.x - hf.x, f.y - hf.y);
    m = *reinterpret_cast<uint32_t*>(&mm2);
}

// ---------------------------------------------------------------------------
// Kernel 0: split prescaled fp32 weights -> 2 fp16 tensors
// ---------------------------------------------------------------------------
__global__ __launch_bounds__(256)
void split_w_kernel(const float* __restrict__ w)
{
    int i = blockIdx.x * 256 + threadIdx.x;           // one float4 per thread
    const int n4 = N_EXPERTS * H_DIM / 4;
    if (i >= n4) return;
    float4 v = reinterpret_cast<const float4*>(w)[i];
    uint32_t h0, m0, h1, m1;
    split2(make_float2(v.x * W_PRESCALE, v.y * W_PRESCALE), h0, m0);
    split2(make_float2(v.z * W_PRESCALE, v.w * W_PRESCALE), h1, m1);
    reinterpret_cast<uint2*>(g_wh)[i] = make_uint2(h0, h1);
    reinterpret_cast<uint2*>(g_wm)[i] = make_uint2(m0, m1);
}

// ---------------------------------------------------------------------------
// Kernel 1: GEMM via mma.sync fp16x2 (4 passes, single accumulator) + RN flush.
// CTA: 128 tokens x 64 experts. BK=32. 3-stage cp.async pipeline. 2 CTAs/SM.
// smem/stage: A fp32 [128][40] (160B rows), B fp16x2 [2][64][40] (80B rows)
// warps: 4(m) x 2(n); warp tile 32 x 32; accum 2x4 m16n8 microtiles.
// ---------------------------------------------------------------------------
#define BM        128
#define BN        64
#define BK        32
#define NCHUNK    (H_DIM / BK)          // 224
#define FLUSH_MASK 7                    // flush every 8 chunks (K=256)
#define A_BYTES   (128 * 160)           // 20480
#define B_SPLIT_B (64 * 80)             // 5120
#define STAGE_B   (A_BYTES + 2 * B_SPLIT_B)  // 30720
#define GEMM_SMEM (3 * STAGE_B)              // 92160

__device__ __forceinline__ void load_stage(const float* __restrict__ x,
                                           int row0, int e0, int k0,
                                           uint32_t stage_base, int tid)
{
    // A: 128 rows x 32 fp32 (128B payload per row, row stride 160B)
#pragma unroll
    for (int l = 0; l < 4; l++) {
        int q = tid + 256 * l;             // 0..1023
        int row = q >> 3, seg = q & 7;
        const float* src = x + (size_t)(row0 + row) * H_DIM + k0 + seg * 4;
        cp16(stage_base + row * 160 + seg * 16, src);
    }
    // B: 2 splits x 64 rows x 32 fp16 (64B payload per row, stride 80B)
#pragma unroll
    for (int l = 0; l < 2; l++) {
        int q = tid + 256 * l;             // 0..511
        int s = q >> 8;                    // split
        int r = q & 255;
        int row = r >> 2, seg = r & 3;
        const __half* wp = s ? g_wm : g_wh;
        const __half* src = wp + (size_t)(e0 + row) * H_DIM + k0 + seg * 8;
        cp16(stage_base + A_BYTES + s * B_SPLIT_B + row * 80 + seg * 16, src);
    }
}

__global__ __launch_bounds__(256, 2)
void moe_gemm_mma(const float* __restrict__ x)
{
    extern __shared__ char smem[];
    const uint32_t sbase = smem_to_u32(smem);
    const int tid  = threadIdx.x;
    const int lane = tid & 31;
    const int wid  = tid >> 5;
    const int wm   = wid & 3;              // warp row (m)
    const int wn   = wid >> 2;             // warp col (n)
    const int row0 = blockIdx.x * BM;
    const int e0   = blockIdx.y * BN;

    float acc[2][4][4];                    // short-chain accumulators
    float master[2][4][4];                 // RN-summed masters
#pragma unroll
    for (int mt = 0; mt < 2; mt++)
#pragma unroll
        for (int nt = 0; nt < 4; nt++)
#pragma unroll
            for (int q = 0; q < 4; q++) { acc[mt][nt][q] = 0.0f; master[mt][nt][q] = 0.0f; }

    // prologue: stages 0,1
    load_stage(x, row0, e0, 0,  sbase + 0 * STAGE_B, tid); CP_COMMIT();
    load_stage(x, row0, e0, BK, sbase + 1 * STAGE_B, tid); CP_COMMIT();

    const int c2 = (lane & 3) * 2;         // k-pair base within 8

    for (int c = 0; c < NCHUNK; ++c) {
        CP_WAIT1();
        __syncthreads();

        if (c + 2 < NCHUNK)
            load_stage(x, row0, e0, (c + 2) * BK, sbase + ((c + 2) % 3) * STAGE_B, tid);
        CP_COMMIT();

        const int slot = c % 3;
        const char* As = smem + slot * STAGE_B;
        const uint32_t Bs = sbase + slot * STAGE_B + A_BYTES;

#pragma unroll
        for (int kk = 0; kk < 2; kk++) {           // two k16 steps per BK=32
            // ---- A fragments: load fp32 pairs, split to fp16x2 ----
            uint32_t ah[2][4], am[2][4];
#pragma unroll
            for (int mt = 0; mt < 2; mt++) {
                int brow = wm * 32 + mt * 16 + (lane >> 2);
#pragma unroll
                for (int q = 0; q < 4; q++) {
                    int r   = brow + (q & 1) * 8;
                    int col = kk * 16 + c2 + (q >> 1) * 8;
                    float2 f = *reinterpret_cast<const float2*>(As + (r * 40 + col) * 4);
                    split2(f, ah[mt][q], am[mt][q]);
                }
            }
            // ---- passes grouped by B split (one b-set live at a time) ----
            // All 4 pass products share uniform scale -> single accumulator.
#pragma unroll
            for (int s = 0; s < 2; s++) {
                uint32_t b[2][4];
#pragma unroll
                for (int p = 0; p < 2; p++) {
                    int row = wn * 32 + p * 16 + (lane & 7) + ((lane >> 4) & 1) * 8;
                    uint32_t addr = Bs + s * B_SPLIT_B + row * 80
                                  + kk * 32 + ((lane >> 3) & 1) * 16;
                    ldmatrix_x4(b[p], addr);
                }
                // a_h x b_s
#pragma unroll
                for (int mt = 0; mt < 2; mt++)
#pragma unroll
                    for (int nt = 0; nt < 4; nt++) {
                        int p = nt >> 1, o = (nt & 1) * 2;
                        mma_fp16(acc[mt][nt], ah[mt], b[p][o], b[p][o + 1]);
                    }
                // a_m x b_s
#pragma unroll
                for (int mt = 0; mt < 2; mt++)
#pragma unroll
                    for (int nt = 0; nt < 4; nt++) {
                        int p = nt >> 1, o = (nt & 1) * 2;
                        mma_fp16(acc[mt][nt], am[mt], b[p][o], b[p][o + 1]);
                    }
            }
        }

        // ---- RN flush: keep tensor-core accumulation chains short ----
        if ((c & FLUSH_MASK) == FLUSH_MASK) {
#pragma unroll
            for (int mt = 0; mt < 2; mt++)
#pragma unroll
                for (int nt = 0; nt < 4; nt++)
#pragma unroll
                    for (int q = 0; q < 4; q++) {
                        master[mt][nt][q] += acc[mt][nt][q];
                        acc[mt][nt][q] = 0.0f;
                    }
        }
    }

    // fold residual (NCHUNK % 8 == 0 -> acc already zero, harmless)
#pragma unroll
    for (int mt = 0; mt < 2; mt++)
#pragma unroll
        for (int nt = 0; nt < 4; nt++)
#pragma unroll
            for (int q = 0; q < 4; q++) master[mt][nt][q] += acc[mt][nt][q];

    // epilogue: write logits (undo W prescale)
#pragma unroll
    for (int mt = 0; mt < 2; mt++) {
        int row = row0 + wm * 32 + mt * 16 + (lane >> 2);
#pragma unroll
        for (int nt = 0; nt < 4; nt++) {
            int col = e0 + wn * 32 + nt * 8 + c2;
            *reinterpret_cast<float2*>(&g_logits[(size_t)row * N_EXPERTS + col]) =
                make_float2(master[mt][nt][0] * W_POSTSCALE,
                            master[mt][nt][1] * W_POSTSCALE);
            *reinterpret_cast<float2*>(&g_logits[(size_t)(row + 8) * N_EXPERTS + col]) =
                make_float2(master[mt][nt][2] * W_POSTSCALE,
                            master[mt][nt][3] * W_POSTSCALE);
        }
    }
}

// ---------------------------------------------------------------------------
// Kernel 2: per-token grouped top-k. One warp per token.
// ---------------------------------------------------------------------------
__global__ __launch_bounds__(256)
void moe_topk_kernel(const float* __restrict__ bias, float* __restrict__ out, int T)
{
    const unsigned FULL = 0xFFFFFFFFu;
    const int lane   = threadIdx.x & 31;
    const int warpId = threadIdx.x >> 5;
    const int t = blockIdx.x * 8 + warpId;
    if (t >= T) return;

    const float* lg = &g_logits[(size_t)t * N_EXPERTS];

    float s[8], sb[8];
#pragma unroll
    for (int j = 0; j < 8; j++) {
        int e = j * 32 + lane;
        float logit = lg[e];
        float sv = 1.0f / (1.0f + expf(-logit));
        s[j]  = sv;
        sb[j] = sv + bias[e];
    }

    float gs[8];
#pragma unroll
    for (int g = 0; g < 8; g++) {
        float m1 = sb[g], m2 = -FLT_MAX;
#pragma unroll
        for (int off = 16; off >= 1; off >>= 1) {
            float o1 = __shfl_xor_sync(FULL, m1, off);
            float o2 = __shfl_xor_sync(FULL, m2, off);
            float hi = fmaxf(m1, o1);
            float lo = fminf(m1, o1);
            m2 = fmaxf(lo, fmaxf(m2, o2));
            m1 = hi;
        }
        gs[g] = m1 + m2;
    }

    unsigned gmask = 0;
#pragma unroll
    for (int r = 0; r < TOPK_GRP; r++) {
        float best = -FLT_MAX; int bg = 0;
#pragma unroll
        for (int g = 0; g < 8; g++) {
            bool taken = (gmask >> g) & 1u;
            if (!taken && gs[g] > best) { best = gs[g]; bg = g; }
        }
        gmask |= (1u << bg);
    }

    float v[8];
#pragma unroll
    for (int j = 0; j < 8; j++)
        v[j] = ((gmask >> j) & 1u) ? sb[j] : -FLT_MAX;

    float wts[TOP_K];
    int   idxs[TOP_K];
    float wsum = 0.0f;
#pragma unroll
    for (int r = 0; r < TOP_K; r++) {
        float bv = -FLT_MAX; int bj = -1;
#pragma unroll
        for (int j = 0; j < 8; j++)
            if (v[j] > bv) { bv = v[j]; bj = j; }
        int bidx = (bj >= 0) ? (bj * 32 + lane) : (N_EXPERTS + lane);

        float cv = bv; int ci = bidx;
#pragma unroll
        for (int off = 16; off >= 1; off >>= 1) {
            float ov = __shfl_xor_sync(FULL, cv, off);
            int   oi = __shfl_xor_sync(FULL, ci, off);
            if (ov > cv || (ov == cv && oi < ci)) { cv = ov; ci = oi; }
        }
        int wl = ci & 31;
        int wj = ci >> 5;
        float sv_local = 0.0f;
#pragma unroll
        for (int j = 0; j < 8; j++) if (j == wj) sv_local = s[j];
        float sv = __shfl_sync(FULL, sv_local, wl);

        idxs[r] = ci;
        wts[r]  = sv;
        wsum   += sv;

        if (lane == wl) {
#pragma unroll
            for (int j = 0; j < 8; j++) if (j == wj) v[j] = -FLT_MAX;
        }
    }

    if (lane == 0) {
        float inv = SCALE / wsum;
        size_t half = (size_t)T * TOP_K;
#pragma unroll
        for (int r = 0; r < TOP_K; r++) {
            out[(size_t)t * TOP_K + r]        = (float)idxs[r];
            out[half + (size_t)t * TOP_K + r] = wts[r] * inv;
        }
    }
}

// ---------------------------------------------------------------------------
extern "C" void kernel_launch(void* const* d_in, const int* in_sizes, int n_in,
                              void* d_out, int out_size)
{
    const float* x    = (const float*)d_in[0];   // [B,S,H] fp32
    const float* w    = (const float*)d_in[1];   // [E,H]   fp32
    const float* bias = (const float*)d_in[2];   // [E]     fp32
    float* out = (float*)d_out;

    const int E = in_sizes[2];                   // 256
    const int H = in_sizes[1] / E;               // 7168
    const int T = in_sizes[0] / H;               // 8192

    // 0) split prescaled weights into fp16x2
    {
        int n4 = E * H / 4;
        split_w_kernel<<<(n4 + 255) / 256, 256>>>(w);
    }

    // 1) tensor-core GEMM -> g_logits
    cudaFuncSetAttribute(moe_gemm_mma,
                         cudaFuncAttributeMaxDynamicSharedMemorySize, GEMM_SMEM);
    dim3 gemmGrid(T / BM, E / BN);               // (64, 4)
    moe_gemm_mma<<<gemmGrid, 256, GEMM_SMEM>>>(x);

    // 2) grouped top-k
    dim3 topkGrid((T + 7) / 8);
    moe_topk_kernel<<<topkGrid, 256>>>(bias, out, T);
}

// round 6
// speedup vs baseline: 2.4285x; 1.1176x over previous
#include <cuda_runtime.h>
#include <cuda_fp16.h>
#include <math.h>
#include <float.h>
#include <stdint.h>

// ============================================================================
// DeepSeekV3 MoE Gate (sm_103a; PTX target compute_103 -> no tcgen05).
// GEMM via mma.sync.m16n8k16 fp16 with fp16x2 split (W prescaled x64 so all
// 4 product passes share one fp32 accumulator) + periodic RN master flush.
// R6: warp tile 32x64, BK=64, 3-stage pipeline, 1 CTA/SM.
//   logits = x @ W^T  (T=8192, H=7168, E=256)
//   then sigmoid/bias/grouped top-k
// Output (float32): [ T*8 indices (as float) | T*8 weights ]
// ============================================================================

#define N_EXPERTS 256
#define TOPK_GRP  4
#define TOP_K     8
#define SCALE     2.5f
#define H_DIM     7168
#define MAX_T     8192
#define W_PRESCALE   64.0f
#define W_POSTSCALE  0.015625f   // 1/64

__device__ float g_logits[MAX_T * N_EXPERTS];                 // 8 MB
__device__ __align__(16) __half g_wh[N_EXPERTS * H_DIM];      // fp16(64*w)
__device__ __align__(16) __half g_wm[N_EXPERTS * H_DIM];      // fp16(64*w - hi)

// ---------------------------------------------------------------------------
// helpers
// ---------------------------------------------------------------------------
__device__ __forceinline__ uint32_t smem_to_u32(const void* p) {
    uint32_t a;
    asm("{ .reg .u64 t; cvta.to.shared.u64 t, %1; cvt.u32.u64 %0, t; }"
        : "=r"(a) : "l"(p));
    return a;
}
__device__ __forceinline__ void cp16(uint32_t dst, const void* src) {
    asm volatile("cp.async.cg.shared.global [%0], [%1], 16;" :: "r"(dst), "l"(src));
}
#define CP_COMMIT() asm volatile("cp.async.commit_group;" ::: "memory")
#define CP_WAIT1()  asm volatile("cp.async.wait_group 1;" ::: "memory")

__device__ __forceinline__ void ldmatrix_x4(uint32_t* r, uint32_t addr) {
    asm volatile("ldmatrix.sync.aligned.m8n8.x4.shared.b16 {%0,%1,%2,%3}, [%4];"
                 : "=r"(r[0]), "=r"(r[1]), "=r"(r[2]), "=r"(r[3]) : "r"(addr));
}
__device__ __forceinline__ void mma_fp16(float* d, const uint32_t* a,
                                         uint32_t b0, uint32_t b1) {
    asm volatile(
        "mma.sync.aligned.m16n8k16.row.col.f32.f16.f16.f32 "
        "{%0,%1,%2,%3}, {%4,%5,%6,%7}, {%8,%9}, {%0,%1,%2,%3};"
        : "+f"(d[0]), "+f"(d[1]), "+f"(d[2]), "+f"(d[3])
        : "r"(a[0]), "r"(a[1]), "r"(a[2]), "r"(a[3]), "r"(b0), "r"(b1));
}

// split a float2 into 2 packed fp16x2 (hi, mid); low 16 bits = f.x
__device__ __forceinline__ void split2(float2 f, uint32_t& h, uint32_t& m) {
    __half2 hh = __floats2half2_rn(f.x, f.y);
    h = *reinterpret_cast<uint32_t*>(&hh);
    float2 hf = __half22float2(hh);
    __half2 mm2 = __floats2half2_rn(f.x - hf.x, f.y - hf.y);
    m = *reinterpret_cast<uint32_t*>(&mm2);
}

// ---------------------------------------------------------------------------
// Kernel 0: split prescaled fp32 weights -> 2 fp16 tensors
// ---------------------------------------------------------------------------
__global__ __launch_bounds__(256)
void split_w_kernel(const float* __restrict__ w)
{
    int i = blockIdx.x * 256 + threadIdx.x;           // one float4 per thread
    const int n4 = N_EXPERTS * H_DIM / 4;
    if (i >= n4) return;
    float4 v = reinterpret_cast<const float4*>(w)[i];
    uint32_t h0, m0, h1, m1;
    split2(make_float2(v.x * W_PRESCALE, v.y * W_PRESCALE), h0, m0);
    split2(make_float2(v.z * W_PRESCALE, v.w * W_PRESCALE), h1, m1);
    reinterpret_cast<uint2*>(g_wh)[i] = make_uint2(h0, h1);
    reinterpret_cast<uint2*>(g_wm)[i] = make_uint2(m0, m1);
}

// ---------------------------------------------------------------------------
// Kernel 1: GEMM via mma.sync fp16x2 (4 passes, single accumulator) + RN flush.
// CTA: 128 tokens x 128 experts. BK=64. 3-stage cp.async pipeline. 1 CTA/SM.
// smem/stage: A fp32 [128][72] (288B rows), B fp16x2 [2][128][144B rows]
// warps: 4(m) x 2(n); warp tile 32 x 64; accum 2x8 m16n8 microtiles.
// ---------------------------------------------------------------------------
#define BM        128
#define BN        128
#define BK        64
#define NCHUNK    (H_DIM / BK)          // 112
#define FLUSH_MASK 3                    // flush every 4 chunks (K=256)
#define A_ROWB    288                   // 72 floats
#define A_BYTES   (128 * A_ROWB)        // 36864
#define B_ROWB    144
#define B_SPLIT_B (128 * B_ROWB)        // 18432
#define STAGE_B   (A_BYTES + 2 * B_SPLIT_B)  // 73728
#define GEMM_SMEM (3 * STAGE_B)              // 221184

__device__ __forceinline__ void load_stage(const float* __restrict__ x,
                                           int row0, int e0, int k0,
                                           uint32_t stage_base, int tid)
{
    // A: 128 rows x 64 fp32 (256B payload/row, stride 288B): 2048 cp16
#pragma unroll
    for (int l = 0; l < 8; l++) {
        int q = tid + 256 * l;             // 0..2047
        int row = q >> 4, seg = q & 15;
        const float* src = x + (size_t)(row0 + row) * H_DIM + k0 + seg * 4;
        cp16(stage_base + row * A_ROWB + seg * 16, src);
    }
    // B: 2 splits x 128 rows x 64 fp16 (128B payload/row, stride 144B): 2048 cp16
#pragma unroll
    for (int l = 0; l < 8; l++) {
        int q = tid + 256 * l;             // 0..2047
        int s = q >> 10;                   // split
        int r = q & 1023;
        int row = r >> 3, seg = r & 7;
        const __half* wp = s ? g_wm : g_wh;
        const __half* src = wp + (size_t)(e0 + row) * H_DIM + k0 + seg * 8;
        cp16(stage_base + A_BYTES + s * B_SPLIT_B + row * B_ROWB + seg * 16, src);
    }
}

__global__ __launch_bounds__(256, 1)
void moe_gemm_mma(const float* __restrict__ x)
{
    extern __shared__ char smem[];
    const uint32_t sbase = smem_to_u32(smem);
    const int tid  = threadIdx.x;
    const int lane = tid & 31;
    const int wid  = tid >> 5;
    const int wm   = wid & 3;              // warp row (m)
    const int wn   = wid >> 2;             // warp col (n)
    const int row0 = blockIdx.x * BM;
    const int e0   = blockIdx.y * BN;

    float acc[2][8][4];                    // short-chain accumulators
    float master[2][8][4];                 // RN-summed masters
#pragma unroll
    for (int mt = 0; mt < 2; mt++)
#pragma unroll
        for (int nt = 0; nt < 8; nt++)
#pragma unroll
            for (int q = 0; q < 4; q++) { acc[mt][nt][q] = 0.0f; master[mt][nt][q] = 0.0f; }

    // prologue: stages 0,1
    load_stage(x, row0, e0, 0,  sbase + 0 * STAGE_B, tid); CP_COMMIT();
    load_stage(x, row0, e0, BK, sbase + 1 * STAGE_B, tid); CP_COMMIT();

    const int c2 = (lane & 3) * 2;         // k-pair base within 8

    for (int c = 0; c < NCHUNK; ++c) {
        CP_WAIT1();
        __syncthreads();

        if (c + 2 < NCHUNK)
            load_stage(x, row0, e0, (c + 2) * BK, sbase + ((c + 2) % 3) * STAGE_B, tid);
        CP_COMMIT();

        const int slot = c % 3;
        const char* As = smem + slot * STAGE_B;
        const uint32_t Bs = sbase + slot * STAGE_B + A_BYTES;

#pragma unroll
        for (int kk = 0; kk < 4; kk++) {           // four k16 steps per BK=64
            // ---- A fragments: load fp32 pairs, split to fp16x2 ----
            uint32_t ah[2][4], am[2][4];
#pragma unroll
            for (int mt = 0; mt < 2; mt++) {
                int brow = wm * 32 + mt * 16 + (lane >> 2);
#pragma unroll
                for (int q = 0; q < 4; q++) {
                    int r   = brow + (q & 1) * 8;
                    int col = kk * 16 + c2 + (q >> 1) * 8;
                    float2 f = *reinterpret_cast<const float2*>(As + r * A_ROWB + col * 4);
                    split2(f, ah[mt][q], am[mt][q]);
                }
            }
            // ---- passes grouped by B split (one b-set live at a time) ----
#pragma unroll
            for (int s = 0; s < 2; s++) {
                uint32_t b[4][4];
#pragma unroll
                for (int p = 0; p < 4; p++) {
                    int row = wn * 64 + p * 16 + (lane & 7) + ((lane >> 4) & 1) * 8;
                    uint32_t addr = Bs + s * B_SPLIT_B + row * B_ROWB
                                  + kk * 32 + ((lane >> 3) & 1) * 16;
                    ldmatrix_x4(b[p], addr);
                }
                // a_h x b_s  (16 independent MMAs)
#pragma unroll
                for (int mt = 0; mt < 2; mt++)
#pragma unroll
                    for (int nt = 0; nt < 8; nt++) {
                        int p = nt >> 1, o = (nt & 1) * 2;
                        mma_fp16(acc[mt][nt], ah[mt], b[p][o], b[p][o + 1]);
                    }
                // a_m x b_s
#pragma unroll
                for (int mt = 0; mt < 2; mt++)
#pragma unroll
                    for (int nt = 0; nt < 8; nt++) {
                        int p = nt >> 1, o = (nt & 1) * 2;
                        mma_fp16(acc[mt][nt], am[mt], b[p][o], b[p][o + 1]);
                    }
            }
        }

        // ---- RN flush: keep tensor-core accumulation chains short ----
        if ((c & FLUSH_MASK) == FLUSH_MASK) {
#pragma unroll
            for (int mt = 0; mt < 2; mt++)
#pragma unroll
                for (int nt = 0; nt < 8; nt++)
#pragma unroll
                    for (int q = 0; q < 4; q++) {
                        master[mt][nt][q] += acc[mt][nt][q];
                        acc[mt][nt][q] = 0.0f;
                    }
        }
    }

    // fold residual (NCHUNK % 4 == 0 -> acc already zero, harmless)
#pragma unroll
    for (int mt = 0; mt < 2; mt++)
#pragma unroll
        for (int nt = 0; nt < 8; nt++)
#pragma unroll
            for (int q = 0; q < 4; q++) master[mt][nt][q] += acc[mt][nt][q];

    // epilogue: write logits (undo W prescale)
#pragma unroll
    for (int mt = 0; mt < 2; mt++) {
        int row = row0 + wm * 32 + mt * 16 + (lane >> 2);
#pragma unroll
        for (int nt = 0; nt < 8; nt++) {
            int col = e0 + wn * 64 + nt * 8 + c2;
            *reinterpret_cast<float2*>(&g_logits[(size_t)row * N_EXPERTS + col]) =
                make_float2(master[mt][nt][0] * W_POSTSCALE,
                            master[mt][nt][1] * W_POSTSCALE);
            *reinterpret_cast<float2*>(&g_logits[(size_t)(row + 8) * N_EXPERTS + col]) =
                make_float2(master[mt][nt][2] * W_POSTSCALE,
                            master[mt][nt][3] * W_POSTSCALE);
        }
    }
}

// ---------------------------------------------------------------------------
// Kernel 2: per-token grouped top-k. One warp per token.
// ---------------------------------------------------------------------------
__global__ __launch_bounds__(256)
void moe_topk_kernel(const float* __restrict__ bias, float* __restrict__ out, int T)
{
    const unsigned FULL = 0xFFFFFFFFu;
    const int lane   = threadIdx.x & 31;
    const int warpId = threadIdx.x >> 5;
    const int t = blockIdx.x * 8 + warpId;
    if (t >= T) return;

    const float* lg = &g_logits[(size_t)t * N_EXPERTS];

    float s[8], sb[8];
#pragma unroll
    for (int j = 0; j < 8; j++) {
        int e = j * 32 + lane;
        float logit = lg[e];
        float sv = 1.0f / (1.0f + expf(-logit));
        s[j]  = sv;
        sb[j] = sv + bias[e];
    }

    float gs[8];
#pragma unroll
    for (int g = 0; g < 8; g++) {
        float m1 = sb[g], m2 = -FLT_MAX;
#pragma unroll
        for (int off = 16; off >= 1; off >>= 1) {
            float o1 = __shfl_xor_sync(FULL, m1, off);
            float o2 = __shfl_xor_sync(FULL, m2, off);
            float hi = fmaxf(m1, o1);
            float lo = fminf(m1, o1);
            m2 = fmaxf(lo, fmaxf(m2, o2));
            m1 = hi;
        }
        gs[g] = m1 + m2;
    }

    unsigned gmask = 0;
#pragma unroll
    for (int r = 0; r < TOPK_GRP; r++) {
        float best = -FLT_MAX; int bg = 0;
#pragma unroll
        for (int g = 0; g < 8; g++) {
            bool taken = (gmask >> g) & 1u;
            if (!taken && gs[g] > best) { best = gs[g]; bg = g; }
        }
        gmask |= (1u << bg);
    }

    float v[8];
#pragma unroll
    for (int j = 0; j < 8; j++)
        v[j] = ((gmask >> j) & 1u) ? sb[j] : -FLT_MAX;

    float wts[TOP_K];
    int   idxs[TOP_K];
    float wsum = 0.0f;
#pragma unroll
    for (int r = 0; r < TOP_K; r++) {
        float bv = -FLT_MAX; int bj = -1;
#pragma unroll
        for (int j = 0; j < 8; j++)
            if (v[j] > bv) { bv = v[j]; bj = j; }
        int bidx = (bj >= 0) ? (bj * 32 + lane) : (N_EXPERTS + lane);

        float cv = bv; int ci = bidx;
#pragma unroll
        for (int off = 16; off >= 1; off >>= 1) {
            float ov = __shfl_xor_sync(FULL, cv, off);
            int   oi = __shfl_xor_sync(FULL, ci, off);
            if (ov > cv || (ov == cv && oi < ci)) { cv = ov; ci = oi; }
        }
        int wl = ci & 31;
        int wj = ci >> 5;
        float sv_local = 0.0f;
#pragma unroll
        for (int j = 0; j < 8; j++) if (j == wj) sv_local = s[j];
        float sv = __shfl_sync(FULL, sv_local, wl);

        idxs[r] = ci;
        wts[r]  = sv;
        wsum   += sv;

        if (lane == wl) {
#pragma unroll
            for (int j = 0; j < 8; j++) if (j == wj) v[j] = -FLT_MAX;
        }
    }

    if (lane == 0) {
        float inv = SCALE / wsum;
        size_t half = (size_t)T * TOP_K;
#pragma unroll
        for (int r = 0; r < TOP_K; r++) {
            out[(size_t)t * TOP_K + r]        = (float)idxs[r];
            out[half + (size_t)t * TOP_K + r] = wts[r] * inv;
        }
    }
}

// ---------------------------------------------------------------------------
extern "C" void kernel_launch(void* const* d_in, const int* in_sizes, int n_in,
                              void* d_out, int out_size)
{
    const float* x    = (const float*)d_in[0];   // [B,S,H] fp32
    const float* w    = (const float*)d_in[1];   // [E,H]   fp32
    const float* bias = (const float*)d_in[2];   // [E]     fp32
    float* out = (float*)d_out;

    const int E = in_sizes[2];                   // 256
    const int H = in_sizes[1] / E;               // 7168
    const int T = in_sizes[0] / H;               // 8192

    // 0) split prescaled weights into fp16x2
    {
        int n4 = E * H / 4;
        split_w_kernel<<<(n4 + 255) / 256, 256>>>(w);
    }

    // 1) tensor-core GEMM -> g_logits
    cudaFuncSetAttribute(moe_gemm_mma,
                         cudaFuncAttributeMaxDynamicSharedMemorySize, GEMM_SMEM);
    dim3 gemmGrid(T / BM, E / BN);               // (64, 2)
    moe_gemm_mma<<<gemmGrid, 256, GEMM_SMEM>>>(x);

    // 2) grouped top-k
    dim3 topkGrid((T + 7) / 8);
    moe_topk_kernel<<<topkGrid, 256>>>(bias, out, T);
}

// round 7
// speedup vs baseline: 2.8958x; 1.1924x over previous
#include <cuda_runtime.h>
#include <cuda_fp16.h>
#include <math.h>
#include <float.h>
#include <stdint.h>

// ============================================================================
// DeepSeekV3 MoE Gate (sm_103a; PTX target compute_103 -> no tcgen05).
// GEMM via mma.sync.m16n8k16 fp16, fp16x2 split, 3 passes (hh, hm, mh — the
// mm pass is provably below the noise floor), W prescaled x64 so all passes
// share one fp32 accumulator, periodic RN master flush.
//   logits = x @ W^T  (T=8192, H=7168, E=256)
//   then sigmoid/bias/grouped top-k
// Output (float32): [ T*8 indices (as float) | T*8 weights ]
// ============================================================================

#define N_EXPERTS 256
#define TOPK_GRP  4
#define TOP_K     8
#define SCALE     2.5f
#define H_DIM     7168
#define MAX_T     8192
#define W_PRESCALE   64.0f
#define W_POSTSCALE  0.015625f   // 1/64

__device__ float g_logits[MAX_T * N_EXPERTS];                 // 8 MB
__device__ __align__(16) __half g_wh[N_EXPERTS * H_DIM];      // fp16(64*w)
__device__ __align__(16) __half g_wm[N_EXPERTS * H_DIM];      // fp16(64*w - hi)

// ---------------------------------------------------------------------------
// helpers
// ---------------------------------------------------------------------------
__device__ __forceinline__ uint32_t smem_to_u32(const void* p) {
    uint32_t a;
    asm("{ .reg .u64 t; cvta.to.shared.u64 t, %1; cvt.u32.u64 %0, t; }"
        : "=r"(a) : "l"(p));
    return a;
}
__device__ __forceinline__ void cp16(uint32_t dst, const void* src) {
    asm volatile("cp.async.cg.shared.global [%0], [%1], 16;" :: "r"(dst), "l"(src));
}
#define CP_COMMIT() asm volatile("cp.async.commit_group;" ::: "memory")
#define CP_WAIT1()  asm volatile("cp.async.wait_group 1;" ::: "memory")

__device__ __forceinline__ void ldmatrix_x4(uint32_t* r, uint32_t addr) {
    asm volatile("ldmatrix.sync.aligned.m8n8.x4.shared.b16 {%0,%1,%2,%3}, [%4];"
                 : "=r"(r[0]), "=r"(r[1]), "=r"(r[2]), "=r"(r[3]) : "r"(addr));
}
__device__ __forceinline__ void mma_fp16(float* d, const uint32_t* a,
                                         uint32_t b0, uint32_t b1) {
    asm volatile(
        "mma.sync.aligned.m16n8k16.row.col.f32.f16.f16.f32 "
        "{%0,%1,%2,%3}, {%4,%5,%6,%7}, {%8,%9}, {%0,%1,%2,%3};"
        : "+f"(d[0]), "+f"(d[1]), "+f"(d[2]), "+f"(d[3])
        : "r"(a[0]), "r"(a[1]), "r"(a[2]), "r"(a[3]), "r"(b0), "r"(b1));
}

// split a float2 into 2 packed fp16x2 (hi, mid); low 16 bits = f.x
__device__ __forceinline__ void split2(float2 f, uint32_t& h, uint32_t& m) {
    __half2 hh = __floats2half2_rn(f.x, f.y);
    h = *reinterpret_cast<uint32_t*>(&hh);
    float2 hf = __half22float2(hh);
    __half2 mm2 = __floats2half2_rn(f.x - hf.x, f.y - hf.y);
    m = *reinterpret_cast<uint32_t*>(&mm2);
}

// ---------------------------------------------------------------------------
// Kernel 0: split prescaled fp32 weights -> 2 fp16 tensors
// ---------------------------------------------------------------------------
__global__ __launch_bounds__(256)
void split_w_kernel(const float* __restrict__ w)
{
    int i = blockIdx.x * 256 + threadIdx.x;           // one float4 per thread
    const int n4 = N_EXPERTS * H_DIM / 4;
    if (i >= n4) return;
    float4 v = reinterpret_cast<const float4*>(w)[i];
    uint32_t h0, m0, h1, m1;
    split2(make_float2(v.x * W_PRESCALE, v.y * W_PRESCALE), h0, m0);
    split2(make_float2(v.z * W_PRESCALE, v.w * W_PRESCALE), h1, m1);
    reinterpret_cast<uint2*>(g_wh)[i] = make_uint2(h0, h1);
    reinterpret_cast<uint2*>(g_wm)[i] = make_uint2(m0, m1);
}

// ---------------------------------------------------------------------------
// Kernel 1: GEMM via mma.sync fp16x2, 3 passes, single accumulator + RN flush.
// CTA: 128 tokens x 128 experts. BK=64. 3-stage cp.async pipeline. 1 CTA/SM.
// smem/stage: A fp32 [128][72] (288B rows), B fp16x2 [2][128][144B rows]
// warps: 4(m) x 2(n); warp tile 32 x 64; accum 2x8 m16n8 microtiles.
// ---------------------------------------------------------------------------
#define BM        128
#define BN        128
#define BK        64
#define NCHUNK    (H_DIM / BK)          // 112
#define FLUSH_MASK 3                    // flush every 4 chunks (K=256)
#define A_ROWB    288                   // 72 floats
#define A_BYTES   (128 * A_ROWB)        // 36864
#define B_ROWB    144
#define B_SPLIT_B (128 * B_ROWB)        // 18432
#define STAGE_B   (A_BYTES + 2 * B_SPLIT_B)  // 73728
#define GEMM_SMEM (3 * STAGE_B)              // 221184

__device__ __forceinline__ void load_stage(const float* __restrict__ x,
                                           int row0, int e0, int k0,
                                           uint32_t stage_base, int tid)
{
    // A: 128 rows x 64 fp32 (256B payload/row, stride 288B): 2048 cp16
#pragma unroll
    for (int l = 0; l < 8; l++) {
        int q = tid + 256 * l;             // 0..2047
        int row = q >> 4, seg = q & 15;
        const float* src = x + (size_t)(row0 + row) * H_DIM + k0 + seg * 4;
        cp16(stage_base + row * A_ROWB + seg * 16, src);
    }
    // B: 2 splits x 128 rows x 64 fp16 (128B payload/row, stride 144B): 2048 cp16
#pragma unroll
    for (int l = 0; l < 8; l++) {
        int q = tid + 256 * l;             // 0..2047
        int s = q >> 10;                   // split
        int r = q & 1023;
        int row = r >> 3, seg = r & 7;
        const __half* wp = s ? g_wm : g_wh;
        const __half* src = wp + (size_t)(e0 + row) * H_DIM + k0 + seg * 8;
        cp16(stage_base + A_BYTES + s * B_SPLIT_B + row * B_ROWB + seg * 16, src);
    }
}

__global__ __launch_bounds__(256, 1)
void moe_gemm_mma(const float* __restrict__ x)
{
    extern __shared__ char smem[];
    const uint32_t sbase = smem_to_u32(smem);
    const int tid  = threadIdx.x;
    const int lane = tid & 31;
    const int wid  = tid >> 5;
    const int wm   = wid & 3;              // warp row (m)
    const int wn   = wid >> 2;             // warp col (n)
    const int row0 = blockIdx.x * BM;
    const int e0   = blockIdx.y * BN;

    float acc[2][8][4];                    // short-chain accumulators
    float master[2][8][4];                 // RN-summed masters
#pragma unroll
    for (int mt = 0; mt < 2; mt++)
#pragma unroll
        for (int nt = 0; nt < 8; nt++)
#pragma unroll
            for (int q = 0; q < 4; q++) { acc[mt][nt][q] = 0.0f; master[mt][nt][q] = 0.0f; }

    // prologue: stages 0,1
    load_stage(x, row0, e0, 0,  sbase + 0 * STAGE_B, tid); CP_COMMIT();
    load_stage(x, row0, e0, BK, sbase + 1 * STAGE_B, tid); CP_COMMIT();

    const int c2 = (lane & 3) * 2;         // k-pair base within 8

    for (int c = 0; c < NCHUNK; ++c) {
        CP_WAIT1();
        __syncthreads();

        if (c + 2 < NCHUNK)
            load_stage(x, row0, e0, (c + 2) * BK, sbase + ((c + 2) % 3) * STAGE_B, tid);
        CP_COMMIT();

        const int slot = c % 3;
        const char* As = smem + slot * STAGE_B;
        const uint32_t Bs = sbase + slot * STAGE_B + A_BYTES;

#pragma unroll
        for (int kk = 0; kk < 4; kk++) {           // four k16 steps per BK=64
            // ---- A fragments: load fp32 pairs, split to fp16x2 ----
            uint32_t ah[2][4], am[2][4];
#pragma unroll
            for (int mt = 0; mt < 2; mt++) {
                int brow = wm * 32 + mt * 16 + (lane >> 2);
#pragma unroll
                for (int q = 0; q < 4; q++) {
                    int r   = brow + (q & 1) * 8;
                    int col = kk * 16 + c2 + (q >> 1) * 8;
                    float2 f = *reinterpret_cast<const float2*>(As + r * A_ROWB + col * 4);
                    split2(f, ah[mt][q], am[mt][q]);
                }
            }
            // ---- 3 passes grouped by B split: s=0 -> ah*bh + am*bh,
            //                                  s=1 -> ah*bm only ----
#pragma unroll
            for (int s = 0; s < 2; s++) {
                uint32_t b[4][4];
#pragma unroll
                for (int p = 0; p < 4; p++) {
                    int row = wn * 64 + p * 16 + (lane & 7) + ((lane >> 4) & 1) * 8;
                    uint32_t addr = Bs + s * B_SPLIT_B + row * B_ROWB
                                  + kk * 32 + ((lane >> 3) & 1) * 16;
                    ldmatrix_x4(b[p], addr);
                }
                // a_h x b_s  (16 independent MMAs)
#pragma unroll
                for (int mt = 0; mt < 2; mt++)
#pragma unroll
                    for (int nt = 0; nt < 8; nt++) {
                        int p = nt >> 1, o = (nt & 1) * 2;
                        mma_fp16(acc[mt][nt], ah[mt], b[p][o], b[p][o + 1]);
                    }
                // a_m x b_h  (skip a_m x b_m: below noise floor)
                if (s == 0) {
#pragma unroll
                    for (int mt = 0; mt < 2; mt++)
#pragma unroll
                        for (int nt = 0; nt < 8; nt++) {
                            int p = nt >> 1, o = (nt & 1) * 2;
                            mma_fp16(acc[mt][nt], am[mt], b[p][o], b[p][o + 1]);
                        }
                }
            }
        }

        // ---- RN flush: keep tensor-core accumulation chains short ----
        if ((c & FLUSH_MASK) == FLUSH_MASK) {
#pragma unroll
            for (int mt = 0; mt < 2; mt++)
#pragma unroll
                for (int nt = 0; nt < 8; nt++)
#pragma unroll
                    for (int q = 0; q < 4; q++) {
                        master[mt][nt][q] += acc[mt][nt][q];
                        acc[mt][nt][q] = 0.0f;
                    }
        }
    }

    // fold residual (NCHUNK % 4 == 0 -> acc already zero, harmless)
#pragma unroll
    for (int mt = 0; mt < 2; mt++)
#pragma unroll
        for (int nt = 0; nt < 8; nt++)
#pragma unroll
            for (int q = 0; q < 4; q++) master[mt][nt][q] += acc[mt][nt][q];

    // epilogue: write logits (undo W prescale)
#pragma unroll
    for (int mt = 0; mt < 2; mt++) {
        int row = row0 + wm * 32 + mt * 16 + (lane >> 2);
#pragma unroll
        for (int nt = 0; nt < 8; nt++) {
            int col = e0 + wn * 64 + nt * 8 + c2;
            *reinterpret_cast<float2*>(&g_logits[(size_t)row * N_EXPERTS + col]) =
                make_float2(master[mt][nt][0] * W_POSTSCALE,
                            master[mt][nt][1] * W_POSTSCALE);
            *reinterpret_cast<float2*>(&g_logits[(size_t)(row + 8) * N_EXPERTS + col]) =
                make_float2(master[mt][nt][2] * W_POSTSCALE,
                            master[mt][nt][3] * W_POSTSCALE);
        }
    }
}

// ---------------------------------------------------------------------------
// Kernel 2: per-token grouped top-k. One warp per token.
// ---------------------------------------------------------------------------
__global__ __launch_bounds__(256)
void moe_topk_kernel(const float* __restrict__ bias, float* __restrict__ out, int T)
{
    const unsigned FULL = 0xFFFFFFFFu;
    const int lane   = threadIdx.x & 31;
    const int warpId = threadIdx.x >> 5;
    const int t = blockIdx.x * 8 + warpId;
    if (t >= T) return;

    const float* lg = &g_logits[(size_t)t * N_EXPERTS];

    float s[8], sb[8];
#pragma unroll
    for (int j = 0; j < 8; j++) {
        int e = j * 32 + lane;
        float logit = lg[e];
        float sv = 1.0f / (1.0f + expf(-logit));
        s[j]  = sv;
        sb[j] = sv + bias[e];
    }

    float gs[8];
#pragma unroll
    for (int g = 0; g < 8; g++) {
        float m1 = sb[g], m2 = -FLT_MAX;
#pragma unroll
        for (int off = 16; off >= 1; off >>= 1) {
            float o1 = __shfl_xor_sync(FULL, m1, off);
            float o2 = __shfl_xor_sync(FULL, m2, off);
            float hi = fmaxf(m1, o1);
            float lo = fminf(m1, o1);
            m2 = fmaxf(lo, fmaxf(m2, o2));
            m1 = hi;
        }
        gs[g] = m1 + m2;
    }

    unsigned gmask = 0;
#pragma unroll
    for (int r = 0; r < TOPK_GRP; r++) {
        float best = -FLT_MAX; int bg = 0;
#pragma unroll
        for (int g = 0; g < 8; g++) {
            bool taken = (gmask >> g) & 1u;
            if (!taken && gs[g] > best) { best = gs[g]; bg = g; }
        }
        gmask |= (1u << bg);
    }

    float v[8];
#pragma unroll
    for (int j = 0; j < 8; j++)
        v[j] = ((gmask >> j) & 1u) ? sb[j] : -FLT_MAX;

    float wts[TOP_K];
    int   idxs[TOP_K];
    float wsum = 0.0f;
#pragma unroll
    for (int r = 0; r < TOP_K; r++) {
        float bv = -FLT_MAX; int bj = -1;
#pragma unroll
        for (int j = 0; j < 8; j++)
            if (v[j] > bv) { bv = v[j]; bj = j; }
        int bidx = (bj >= 0) ? (bj * 32 + lane) : (N_EXPERTS + lane);

        float cv = bv; int ci = bidx;
#pragma unroll
        for (int off = 16; off >= 1; off >>= 1) {
            float ov = __shfl_xor_sync(FULL, cv, off);
            int   oi = __shfl_xor_sync(FULL, ci, off);
            if (ov > cv || (ov == cv && oi < ci)) { cv = ov; ci = oi; }
        }
        int wl = ci & 31;
        int wj = ci >> 5;
        float sv_local = 0.0f;
#pragma unroll
        for (int j = 0; j < 8; j++) if (j == wj) sv_local = s[j];
        float sv = __shfl_sync(FULL, sv_local, wl);

        idxs[r] = ci;
        wts[r]  = sv;
        wsum   += sv;

        if (lane == wl) {
#pragma unroll
            for (int j = 0; j < 8; j++) if (j == wj) v[j] = -FLT_MAX;
        }
    }

    if (lane == 0) {
        float inv = SCALE / wsum;
        size_t half = (size_t)T * TOP_K;
#pragma unroll
        for (int r = 0; r < TOP_K; r++) {
            out[(size_t)t * TOP_K + r]        = (float)idxs[r];
            out[half + (size_t)t * TOP_K + r] = wts[r] * inv;
        }
    }
}

// ---------------------------------------------------------------------------
extern "C" void kernel_launch(void* const* d_in, const int* in_sizes, int n_in,
                              void* d_out, int out_size)
{
    const float* x    = (const float*)d_in[0];   // [B,S,H] fp32
    const float* w    = (const float*)d_in[1];   // [E,H]   fp32
    const float* bias = (const float*)d_in[2];   // [E]     fp32
    float* out = (float*)d_out;

    const int E = in_sizes[2];                   // 256
    const int H = in_sizes[1] / E;               // 7168
    const int T = in_sizes[0] / H;               // 8192

    // 0) split prescaled weights into fp16x2
    {
        int n4 = E * H / 4;
        split_w_kernel<<<(n4 + 255) / 256, 256>>>(w);
    }

    // 1) tensor-core GEMM -> g_logits
    cudaFuncSetAttribute(moe_gemm_mma,
                         cudaFuncAttributeMaxDynamicSharedMemorySize, GEMM_SMEM);
    dim3 gemmGrid(T / BM, E / BN);               // (64, 2)
    moe_gemm_mma<<<gemmGrid, 256, GEMM_SMEM>>>(x);

    // 2) grouped top-k
    dim3 topkGrid((T + 7) / 8);
    moe_topk_kernel<<<topkGrid, 256>>>(bias, out, T);
}